// round 6
// baseline (speedup 1.0000x reference)
#include <cuda_runtime.h>
#include <cuda_bf16.h>
#include <cstdint>

#define Bc   2
#define Nc   4096
#define Kc   16
#define CINc 128
#define Dc   256
#define PHc  64
#define AHc  1024
#define Pc   (Nc*Kc)   /* 65536 */
#define EPSc 1e-5f
#define NCH  16
#define CH   256

typedef unsigned long long ull;

// ---------------- packed f32x2 helpers (used in build) ----------------
__device__ __forceinline__ ull pk2(float a, float b){
    ull r; asm("mov.b64 %0,{%1,%2};" : "=l"(r) : "f"(a), "f"(b)); return r;
}
__device__ __forceinline__ void upk2(ull v, float& a, float& b){
    asm("mov.b64 {%0,%1},%2;" : "=f"(a), "=f"(b) : "l"(v));
}
__device__ __forceinline__ ull fma2(ull a, ull b, ull c){
    ull d; asm("fma.rn.f32x2 %0,%1,%2,%3;" : "=l"(d) : "l"(a), "l"(b), "l"(c)); return d;
}

__device__ __forceinline__ uint32_t smem_u32(const void* p){
    uint32_t a; asm("{ .reg .u64 t; cvta.to.shared.u64 t, %1; cvt.u32.u64 %0, t; }" : "=r"(a) : "l"(p));
    return a;
}

// ---------------- warp-MMA + cp.async helpers (baseline PTX, works at compute_103) ----------------
#define LDSM_X4(r, a) \
    asm volatile("ldmatrix.sync.aligned.m8n8.x4.shared.b16 {%0,%1,%2,%3}, [%4];" \
        : "=r"((r)[0]), "=r"((r)[1]), "=r"((r)[2]), "=r"((r)[3]) : "r"(a))

#define MMA16816(d, a, b0, b1) \
    asm volatile("mma.sync.aligned.m16n8k16.row.col.f32.bf16.bf16.f32 " \
        "{%0,%1,%2,%3},{%4,%5,%6,%7},{%8,%9},{%0,%1,%2,%3};" \
        : "+f"((d)[0]), "+f"((d)[1]), "+f"((d)[2]), "+f"((d)[3]) \
        : "r"((a)[0]), "r"((a)[1]), "r"((a)[2]), "r"((a)[3]), "r"(b0), "r"(b1))

#define CP_ASYNC16(dst, src) \
    asm volatile("cp.async.cg.shared.global [%0], [%1], 16;" :: "r"(dst), "l"(src))
#define CP_COMMIT() asm volatile("cp.async.commit_group;" ::: "memory")
#define CP_WAIT1()  asm volatile("cp.async.wait_group 1;" ::: "memory")
#define CP_WAIT0()  asm volatile("cp.async.wait_group 0;" ::: "memory")

// ---------------- device scratch ----------------
__device__ float g_Wk[Dc*CINc], g_Wv[Dc*CINc], g_Wq[Dc*CINc];
__device__ float g_bk2[Dc], g_bv2[Dc], g_bq2[Dc];
__device__ float g_Wa1f[AHc*Dc];
__device__ float g_ba1f[AHc];
__device__ float g_Wp1f[PHc*3];
__device__ float g_bp1f[PHc];
__device__ __nv_bfloat16 g_Wa1h[AHc*Dc];   // [j][k] row-major
__device__ __nv_bfloat16 g_Wa2h[Dc*AHc];   // [c][j] row-major
__device__ float g_key[Bc*Nc*Dc];   // point-major (b,n,c)
__device__ float g_valv[Bc*Nc*Dc];  // point-major
__device__ float g_qry[Bc*Nc*Dc];   // point-major
__device__ int   g_idx[Bc*Nc*Kc];
__device__ float g_pd[(size_t)Bc*NCH*Nc*16];   // partial knn dists
__device__ int   g_pi[(size_t)Bc*NCH*Nc*16];   // partial knn indices
__device__ __nv_bfloat16 g_Xh[(size_t)Bc*Pc*Dc];  // (b,p,c) bf16: qk_rel+pe
__device__ float g_PE[(size_t)Bc*Pc*Dc];          // (b,p,c) fp32: pe
__device__ __nv_bfloat16 g_H[(size_t)Bc*Pc*AHc];  // (b,p,j) bf16: relu hidden
__device__ float g_agg[Bc*Dc*Nc];                 // (b,c,n)

// ---------------- weight composition ----------------
__global__ void compose_kernel(const float* __restrict__ Wk, const float* __restrict__ bk,
                               const float* __restrict__ Wq, const float* __restrict__ bq,
                               const float* __restrict__ Wv, const float* __restrict__ bv,
                               const float* __restrict__ W_lsq, const float* __restrict__ b_lsq,
                               const float* __restrict__ W_lso, const float* __restrict__ b_lso)
{
    int id = blockIdx.x*256 + threadIdx.x;
    const int total = 3*Dc*CINc;
    if (id < total) {
        int which = id / (Dc*CINc);
        int r = id % (Dc*CINc);
        int o = r / CINc, i = r % CINc;
        const float* A = (which==0) ? Wk : ((which==1) ? Wv : Wq);
        const float* L = (which==2) ? W_lsq : W_lso;
        float s = 0.f;
        #pragma unroll 4
        for (int t = 0; t < Dc; t++) s = fmaf(A[o*Dc+t], L[t*CINc+i], s);
        float* Od = (which==0) ? g_Wk : ((which==1) ? g_Wv : g_Wq);
        Od[o*CINc+i] = s;
    } else if (id < total + 3*Dc) {
        int r = id - total; int which = r / Dc; int o = r % Dc;
        const float* A  = (which==0) ? Wk : ((which==1) ? Wv : Wq);
        const float* bb = (which==0) ? bk : ((which==1) ? bv : bq);
        const float* lb = (which==2) ? b_lsq : b_lso;
        float s = bb[o];
        #pragma unroll 4
        for (int t = 0; t < Dc; t++) s = fmaf(A[o*Dc+t], lb[t], s);
        float* Od = (which==0) ? g_bk2 : ((which==1) ? g_bv2 : g_bq2);
        Od[o] = s;
    }
}

// ---------------- BN folding ----------------
__global__ void fold_kernel(const float* __restrict__ Wa1, const float* __restrict__ ba1,
                            const float* __restrict__ g2,  const float* __restrict__ bt2,
                            const float* __restrict__ m2,  const float* __restrict__ v2,
                            const float* __restrict__ Wp1, const float* __restrict__ bp1,
                            const float* __restrict__ g1,  const float* __restrict__ bt1,
                            const float* __restrict__ m1,  const float* __restrict__ v1)
{
    int id = blockIdx.x*256 + threadIdx.x;
    if (id < AHc*Dc) {
        int j = id / Dc;
        float sc = g2[j] * rsqrtf(v2[j] + EPSc);
        g_Wa1f[id] = sc * Wa1[id];
        return;
    }
    int r = id - AHc*Dc;
    if (r < AHc) {
        float sc = g2[r] * rsqrtf(v2[r] + EPSc);
        g_ba1f[r] = sc*ba1[r] + bt2[r] - m2[r]*sc;
        return;
    }
    r -= AHc;
    if (r < PHc*3) {
        int j = r / 3;
        float sc = g1[j] * rsqrtf(v1[j] + EPSc);
        g_Wp1f[r] = sc * Wp1[r];
        return;
    }
    r -= PHc*3;
    if (r < PHc) {
        float sc = g1[r] * rsqrtf(v1[r] + EPSc);
        g_bp1f[r] = sc*bp1[r] + bt1[r] - m1[r]*sc;
    }
}

// ---------------- bf16 weight conversion (after fold) ----------------
__global__ void tobf16_kernel(const float* __restrict__ Wa2)
{
    int i = blockIdx.x*256 + threadIdx.x;
    if (i < AHc*Dc) {
        g_Wa1h[i] = __float2bfloat16(g_Wa1f[i]);
        g_Wa2h[i] = __float2bfloat16(Wa2[i]);
    }
}

// ---------------- KNN part 1: per-chunk top-16 (256 candidates/chunk) ----------------
__global__ void knn_part_kernel(const float* __restrict__ pos)
{
    __shared__ __align__(16) float4 sc[CH];
    int b = blockIdx.z, ch = blockIdx.y;
    int tid = threadIdx.x;
    int c0 = ch * CH;
    for (int q = tid; q < CH; q += 256) {
        float x = pos[(b*3+0)*Nc + c0 + q];
        float y = pos[(b*3+1)*Nc + c0 + q];
        float z = pos[(b*3+2)*Nc + c0 + q];
        sc[q] = make_float4(x, y, z, fmaf(z, z, fmaf(y, y, x*x)));
    }
    __syncthreads();
    int n = blockIdx.x*256 + tid;
    float qx = pos[(b*3+0)*Nc + n];
    float qy = pos[(b*3+1)*Nc + n];
    float qz = pos[(b*3+2)*Nc + n];
    float qs = fmaf(qz, qz, fmaf(qy, qy, qx*qx));

    float bd[16]; int bi[16];
    #pragma unroll
    for (int t = 0; t < 16; t++) { bd[t] = 3.4e38f; bi[t] = 0; }
    float mx = 3.4e38f; int mp = 0;
    for (int m = 0; m < CH; m++) {
        float4 c = sc[m];
        float dot = fmaf(qz, c.z, fmaf(qy, c.y, qx*c.x));
        float d = (qs + c.w) - 2.0f*dot;
        if (d < mx) {
            bd[mp] = d; bi[mp] = c0 + m;
            mx = bd[0]; mp = 0;
            #pragma unroll
            for (int t = 1; t < 16; t++) if (bd[t] > mx) { mx = bd[t]; mp = t; }
        }
    }
    size_t base = ((size_t)(b*NCH + ch)*Nc + n)*16;
    #pragma unroll
    for (int t = 0; t < 16; t++) { g_pd[base + t] = bd[t]; g_pi[base + t] = bi[t]; }
}

// ---------------- KNN part 2: merge NCHx16 partials (chunk-ascending = index-ascending) ----------------
__global__ void knn_merge_kernel()
{
    int id = blockIdx.x*256 + threadIdx.x;   // 0 .. Bc*Nc-1
    int b = id >> 12, n = id & (Nc-1);
    float bd[16]; int bi[16];
    #pragma unroll
    for (int t = 0; t < 16; t++) { bd[t] = 3.4e38f; bi[t] = 0; }
    float mx = 3.4e38f; int mp = 0;
    for (int ch = 0; ch < NCH; ch++) {
        size_t base = ((size_t)(b*NCH + ch)*Nc + n)*16;
        #pragma unroll
        for (int t = 0; t < 16; t++) {
            float d = g_pd[base + t];
            if (d < mx) {
                bd[mp] = d; bi[mp] = g_pi[base + t];
                mx = bd[0]; mp = 0;
                #pragma unroll
                for (int u = 1; u < 16; u++) if (bd[u] > mx) { mx = bd[u]; mp = u; }
            }
        }
    }
    #pragma unroll
    for (int t = 0; t < 16; t++) g_idx[(b*Nc+n)*16 + t] = bi[t];
}

// ---------------- tiled fp32 GEMM (small pre/post convs) ----------------
template<int O, int I, bool POINT_MAJOR>
__global__ void gemm_kernel(const float* __restrict__ W, const float* __restrict__ bias,
                            const float* __restrict__ In, float* __restrict__ Out)
{
    __shared__ float Wt[64][33];
    __shared__ float Xt[32][64];
    int b  = blockIdx.z;
    int n0 = blockIdx.x*64, o0 = blockIdx.y*64;
    int tid = threadIdx.x, tx = tid & 15, ty = tid >> 4;
    float acc[4][4];
    #pragma unroll
    for (int r = 0; r < 4; r++)
        #pragma unroll
        for (int c = 0; c < 4; c++) acc[r][c] = 0.f;

    for (int k0 = 0; k0 < I; k0 += 32) {
        for (int q = tid; q < 64*32; q += 256) {
            int oo = q >> 5, kk = q & 31;
            Wt[oo][kk] = W[(o0+oo)*I + k0 + kk];
        }
        for (int q = tid; q < 32*64; q += 256) {
            int kk = q >> 6, nn = q & 63;
            Xt[kk][nn] = In[((size_t)b*I + k0 + kk)*Nc + n0 + nn];
        }
        __syncthreads();
        #pragma unroll 8
        for (int kk = 0; kk < 32; kk++) {
            float a[4], bb[4];
            #pragma unroll
            for (int r = 0; r < 4; r++) a[r]  = Wt[ty*4+r][kk];
            #pragma unroll
            for (int c = 0; c < 4; c++) bb[c] = Xt[kk][tx*4+c];
            #pragma unroll
            for (int r = 0; r < 4; r++)
                #pragma unroll
                for (int c = 0; c < 4; c++) acc[r][c] = fmaf(a[r], bb[c], acc[r][c]);
        }
        __syncthreads();
    }
    #pragma unroll
    for (int r = 0; r < 4; r++) {
        float bv = bias[o0 + ty*4 + r];
        #pragma unroll
        for (int c = 0; c < 4; c++) {
            float v = acc[r][c] + bv;
            int oo = o0 + ty*4 + r, nn = n0 + tx*4 + c;
            if (POINT_MAJOR)
                Out[((size_t)b*Nc + nn)*O + oo] = v;
            else
                Out[((size_t)b*O + oo)*Nc + nn] = v;
        }
    }
}

// ---------------- build X (bf16) = q - k_gather + pe, PE (fp32) = pe ----------------
__global__ void build_kernel(const float* __restrict__ pos,
                             const float* __restrict__ Wp2,
                             const float* __restrict__ bp2)
{
    __shared__ float pr[3][64];
    __shared__ __align__(16) float sh[PHc*64];
    __shared__ int sidx[64];
    int b = blockIdx.y;
    int nbase = blockIdx.x*4;
    int pbase = nbase*16;
    int tid = threadIdx.x;

    if (tid < 64) sidx[tid] = g_idx[(b*Nc + nbase)*16 + tid];
    __syncthreads();
    if (tid < 192) {
        int d = tid >> 6, pp = tid & 63;
        int n  = nbase + (pp >> 4);
        int nb = sidx[pp];
        pr[d][pp] = pos[(b*3+d)*Nc + n] - pos[(b*3+d)*Nc + nb];
    }
    __syncthreads();
    for (int q = tid; q < PHc*64; q += 256) {
        int j = q >> 6, pp = q & 63;
        float h = fmaf(g_Wp1f[j*3+2], pr[2][pp],
                  fmaf(g_Wp1f[j*3+1], pr[1][pp],
                  fmaf(g_Wp1f[j*3+0], pr[0][pp], g_bp1f[j])));
        sh[q] = fmaxf(h, 0.f);
    }
    __syncthreads();

    int c = tid;
    float q4[4];
    #pragma unroll
    for (int l = 0; l < 4; l++) q4[l] = g_qry[((size_t)b*Nc + nbase + l)*Dc + c];
    float bc = bp2[c];

    ull A[32];
    #pragma unroll
    for (int g = 0; g < 32; g++) A[g] = pk2(bc, bc);
    const ull* HP = (const ull*)sh;
    #pragma unroll 2
    for (int j = 0; j < PHc; j++) {
        float w = Wp2[c*PHc + j];
        ull wb = pk2(w, w);
        const ull* hp = HP + j*32;
        #pragma unroll
        for (int g = 0; g < 32; g++) A[g] = fma2(wb, hp[g], A[g]);
    }
    #pragma unroll
    for (int g = 0; g < 32; g++) {
        float p0, p1; upk2(A[g], p0, p1);
        int pp0 = g*2;
        #pragma unroll
        for (int u = 0; u < 2; u++) {
            int pp = pp0 + u;
            float pe = (u == 0) ? p0 : p1;
            int nb = sidx[pp];
            int nl = pp >> 4;
            size_t kb = ((size_t)b*Nc + nb)*Dc + c;
            size_t ob = ((size_t)b*Pc + pbase + pp)*Dc + c;
            g_Xh[ob] = __float2bfloat16(q4[nl] - g_key[kb] + pe);
            g_PE[ob] = pe;
        }
    }
}

// ---------------- warp-MMA core with cp.async double buffering ----------------
// acc[p 128 x n 256] += A[128 x K] · B[256 x K]^T
// Block: 512 threads = 16 warps (8 row-warps x 2 col-warps).
// smem: A buffers [2][128*SMPITCH], B buffers [2][256*SMPITCH] = 110592 B.
#define SMPITCH 144
#define SMEM_MMA (2*128*SMPITCH + 2*256*SMPITCH)   /* 110592 B */

template<int KTOT>
__device__ __forceinline__ void mma_core(char* sm,
                                         const __nv_bfloat16* __restrict__ gA,
                                         const __nv_bfloat16* __restrict__ gB,
                                         float (&acc)[16][4])
{
    uint32_t sA = smem_u32(sm);
    uint32_t sB = sA + 2*128*SMPITCH;
    int tid = threadIdx.x;
    int lane = tid & 31, wid = tid >> 5;
    int wr = wid >> 1, wc = wid & 1;

    uint32_t aOff = (uint32_t)(wr*16 + (lane & 15))*SMPITCH + (uint32_t)((lane >> 4) << 4);
    uint32_t bOff = (uint32_t)(wc*128 + (lane & 15))*SMPITCH + (uint32_t)((lane >> 4) << 4);

    const int NS = KTOT/64;
    int arow = tid >> 3, ac8 = (tid & 7) << 3;     // A: 2 iters cover 128 rows
    // issue slice s into buffer buf
    #define MMA_ISSUE(s, buf) do { \
        uint32_t dA = sA + (buf)*(128*SMPITCH); \
        uint32_t dB = sB + (buf)*(256*SMPITCH); \
        _Pragma("unroll") \
        for (int it = 0; it < 2; it++) { \
            int row = arow + it*64; \
            CP_ASYNC16(dA + row*SMPITCH + ac8*2, gA + (size_t)row*KTOT + (s)*64 + ac8); \
        } \
        _Pragma("unroll") \
        for (int it = 0; it < 4; it++) { \
            int row = arow + it*64; \
            CP_ASYNC16(dB + row*SMPITCH + ac8*2, gB + (size_t)row*KTOT + (s)*64 + ac8); \
        } \
        CP_COMMIT(); \
    } while(0)

    MMA_ISSUE(0, 0);
    for (int i = 0; i < NS; i++) {
        if (i + 1 < NS) { MMA_ISSUE(i+1, (i+1)&1); CP_WAIT1(); }
        else            { CP_WAIT0(); }
        __syncthreads();
        uint32_t aAddr = sA + (i&1)*(128*SMPITCH) + aOff;
        uint32_t bAddr = sB + (i&1)*(256*SMPITCH) + bOff;
        #pragma unroll
        for (int ks = 0; ks < 4; ks++) {
            uint32_t a[4];
            LDSM_X4(a, aAddr + ks*32);
            #pragma unroll
            for (int tp = 0; tp < 8; tp++) {
                uint32_t q[4];
                LDSM_X4(q, bAddr + tp*16*SMPITCH + ks*32);
                MMA16816(acc[2*tp],   a, q[0], q[2]);
                MMA16816(acc[2*tp+1], a, q[1], q[3]);
            }
        }
        __syncthreads();
    }
    #undef MMA_ISSUE
}

// ---------------- mlp1: H = relu(X · Wa1^T + b1) -> bf16 ----------------
__global__ void __launch_bounds__(512, 1) mlp1_kernel()
{
    extern __shared__ __align__(16) char sm1[];
    int b = blockIdx.z;
    int ptile = blockIdx.x*128;
    int j0 = blockIdx.y*256;
    const __nv_bfloat16* gA = g_Xh + ((size_t)b*Pc + ptile)*Dc;
    const __nv_bfloat16* gB = g_Wa1h + (size_t)j0*Dc;

    float acc[16][4];
    #pragma unroll
    for (int t = 0; t < 16; t++)
        #pragma unroll
        for (int q = 0; q < 4; q++) acc[t][q] = 0.f;

    mma_core<Dc>(sm1, gA, gB, acc);

    int tid = threadIdx.x, lane = tid & 31, wid = tid >> 5;
    int wr = wid >> 1, wc = wid & 1;
    int prow = ptile + wr*16 + (lane >> 2);
    __nv_bfloat16* H0 = g_H + ((size_t)b*Pc + prow)*AHc + j0;
    __nv_bfloat16* H1 = H0 + (size_t)8*AHc;
    #pragma unroll
    for (int t = 0; t < 16; t++) {
        int c = wc*128 + t*8 + ((lane & 3) << 1);
        float b0 = g_ba1f[j0 + c], b1 = g_ba1f[j0 + c + 1];
        float r00 = fmaxf(acc[t][0] + b0, 0.f);
        float r01 = fmaxf(acc[t][1] + b1, 0.f);
        float r10 = fmaxf(acc[t][2] + b0, 0.f);
        float r11 = fmaxf(acc[t][3] + b1, 0.f);
        uint32_t u0, u1;
        asm("cvt.rn.bf16x2.f32 %0, %1, %2;" : "=r"(u0) : "f"(r01), "f"(r00));
        asm("cvt.rn.bf16x2.f32 %0, %1, %2;" : "=r"(u1) : "f"(r11), "f"(r10));
        *(uint32_t*)(H0 + c) = u0;
        *(uint32_t*)(H1 + c) = u1;
    }
}

// ---------------- mlp2: logits = H · Wa2^T, fused softmax(K=16) + aggregate ----------------
__global__ void __launch_bounds__(512, 1) mlp2_kernel()
{
    extern __shared__ __align__(16) char sm2[];
    int b = blockIdx.z;
    int ptile = blockIdx.x*128;
    const __nv_bfloat16* gA = g_H + ((size_t)b*Pc + ptile)*AHc;
    const __nv_bfloat16* gB = g_Wa2h;

    float acc[16][4];
    #pragma unroll
    for (int t = 0; t < 16; t++)
        #pragma unroll
        for (int q = 0; q < 4; q++) acc[t][q] = 0.f;

    mma_core<AHc>(sm2, gA, gB, acc);

    int tid = threadIdx.x, lane = tid & 31, wid = tid >> 5;
    int wr = wid >> 1, wc = wid & 1;
    int n = (ptile >> 4) + wr;
    const float* peRow = g_PE + ((size_t)b*Pc + ptile + wr*16 + (lane >> 2))*Dc;
    const float* valRow = g_valv + ((size_t)b*Nc + n)*Dc;
    float* aggCol = g_agg + (size_t)b*Dc*Nc + n;

    #pragma unroll
    for (int t = 0; t < 16; t++) {
        int c = wc*128 + t*8 + ((lane & 3) << 1);
        float m0 = fmaxf(acc[t][0], acc[t][2]);
        float m1 = fmaxf(acc[t][1], acc[t][3]);
        #pragma unroll
        for (int d = 4; d <= 16; d <<= 1) {
            m0 = fmaxf(m0, __shfl_xor_sync(0xffffffffu, m0, d));
            m1 = fmaxf(m1, __shfl_xor_sync(0xffffffffu, m1, d));
        }
        float e0 = __expf(acc[t][0] - m0), e2 = __expf(acc[t][2] - m0);
        float e1 = __expf(acc[t][1] - m1), e3 = __expf(acc[t][3] - m1);
        float s0 = e0 + e2, s1 = e1 + e3;
        #pragma unroll
        for (int d = 4; d <= 16; d <<= 1) {
            s0 += __shfl_xor_sync(0xffffffffu, s0, d);
            s1 += __shfl_xor_sync(0xffffffffu, s1, d);
        }
        float2 p0 = *(const float2*)(peRow + c);
        float2 p1 = *(const float2*)(peRow + 8*Dc + c);
        float a0 = e0*p0.x + e2*p1.x;
        float a1 = e1*p0.y + e3*p1.y;
        #pragma unroll
        for (int d = 4; d <= 16; d <<= 1) {
            a0 += __shfl_xor_sync(0xffffffffu, a0, d);
            a1 += __shfl_xor_sync(0xffffffffu, a1, d);
        }
        if (lane < 4) {
            aggCol[(size_t)c*Nc]       = a0/s0 + valRow[c];
            aggCol[(size_t)(c+1)*Nc]   = a1/s1 + valRow[c+1];
        }
    }
}

// ---------------- launch ----------------
extern "C" void kernel_launch(void* const* d_in, const int* in_sizes, int n_in,
                              void* d_out, int out_size)
{
    const float* obj   = (const float*)d_in[0];
    const float* pos   = (const float*)d_in[1];
    const float* qp    = (const float*)d_in[2];
    const float* W_lsq = (const float*)d_in[3];  const float* b_lsq = (const float*)d_in[4];
    const float* W_lso = (const float*)d_in[5];  const float* b_lso = (const float*)d_in[6];
    const float* Wk    = (const float*)d_in[7];  const float* bk    = (const float*)d_in[8];
    const float* Wq    = (const float*)d_in[9];  const float* bq    = (const float*)d_in[10];
    const float* Wv    = (const float*)d_in[11]; const float* bv    = (const float*)d_in[12];
    const float* Wp1   = (const float*)d_in[13]; const float* bp1   = (const float*)d_in[14];
    const float* g1    = (const float*)d_in[15]; const float* bt1   = (const float*)d_in[16];
    const float* m1    = (const float*)d_in[17]; const float* v1    = (const float*)d_in[18];
    const float* Wp2   = (const float*)d_in[19]; const float* bp2   = (const float*)d_in[20];
    const float* Wa1   = (const float*)d_in[21]; const float* ba1   = (const float*)d_in[22];
    const float* g2    = (const float*)d_in[23]; const float* bt2   = (const float*)d_in[24];
    const float* m2    = (const float*)d_in[25]; const float* v2    = (const float*)d_in[26];
    const float* Wa2   = (const float*)d_in[27]; /* ba2 (d_in[28]) cancels in softmax */
    const float* We    = (const float*)d_in[29]; const float* bfin  = (const float*)d_in[30];
    float* out = (float*)d_out;

    cudaFuncSetAttribute(mlp1_kernel, cudaFuncAttributeMaxDynamicSharedMemorySize, SMEM_MMA);
    cudaFuncSetAttribute(mlp2_kernel, cudaFuncAttributeMaxDynamicSharedMemorySize, SMEM_MMA);

    void *pWk, *pWv, *pWq, *pbk, *pbv, *pbq, *pkey, *pval, *pqry, *pagg;
    cudaGetSymbolAddress(&pWk, g_Wk);   cudaGetSymbolAddress(&pWv, g_Wv);
    cudaGetSymbolAddress(&pWq, g_Wq);   cudaGetSymbolAddress(&pbk, g_bk2);
    cudaGetSymbolAddress(&pbv, g_bv2);  cudaGetSymbolAddress(&pbq, g_bq2);
    cudaGetSymbolAddress(&pkey, g_key); cudaGetSymbolAddress(&pval, g_valv);
    cudaGetSymbolAddress(&pqry, g_qry); cudaGetSymbolAddress(&pagg, g_agg);

    compose_kernel<<<387, 256>>>(Wk, bk, Wq, bq, Wv, bv, W_lsq, b_lsq, W_lso, b_lso);
    fold_kernel<<<1029, 256>>>(Wa1, ba1, g2, bt2, m2, v2, Wp1, bp1, g1, bt1, m1, v1);
    tobf16_kernel<<<1024, 256>>>(Wa2);

    knn_part_kernel<<<dim3(Nc/256, NCH, Bc), 256>>>(pos);
    knn_merge_kernel<<<Bc*Nc/256, 256>>>();

    gemm_kernel<Dc, CINc, true><<<dim3(Nc/64, Dc/64, Bc), 256>>>((const float*)pWk, (const float*)pbk, obj, (float*)pkey);
    gemm_kernel<Dc, CINc, true><<<dim3(Nc/64, Dc/64, Bc), 256>>>((const float*)pWv, (const float*)pbv, obj, (float*)pval);
    gemm_kernel<Dc, CINc, true><<<dim3(Nc/64, Dc/64, Bc), 256>>>((const float*)pWq, (const float*)pbq, qp,  (float*)pqry);

    build_kernel<<<dim3(Nc/4, Bc), 256>>>(pos, Wp2, bp2);

    mlp1_kernel<<<dim3(Pc/128, AHc/256, Bc), 512, SMEM_MMA>>>();
    mlp2_kernel<<<dim3(Pc/128, 1, Bc), 512, SMEM_MMA>>>();

    gemm_kernel<CINc, Dc, false><<<dim3(Nc/64, CINc/64, Bc), 256>>>(We, bfin, (const float*)pagg, out);
}

// round 7
// speedup vs baseline: 1.0769x; 1.0769x over previous
#include <cuda_runtime.h>
#include <cuda_bf16.h>
#include <cstdint>

#define Bc   2
#define Nc   4096
#define Kc   16
#define CINc 128
#define Dc   256
#define PHc  64
#define AHc  1024
#define Pc   (Nc*Kc)   /* 65536 */
#define EPSc 1e-5f
#define NCH  8
#define CH   512

typedef unsigned long long ull;

// ---------------- packed f32x2 helpers (used in build) ----------------
__device__ __forceinline__ ull pk2(float a, float b){
    ull r; asm("mov.b64 %0,{%1,%2};" : "=l"(r) : "f"(a), "f"(b)); return r;
}
__device__ __forceinline__ void upk2(ull v, float& a, float& b){
    asm("mov.b64 {%0,%1},%2;" : "=f"(a), "=f"(b) : "l"(v));
}
__device__ __forceinline__ ull fma2(ull a, ull b, ull c){
    ull d; asm("fma.rn.f32x2 %0,%1,%2,%3;" : "=l"(d) : "l"(a), "l"(b), "l"(c)); return d;
}

__device__ __forceinline__ uint32_t smem_u32(const void* p){
    uint32_t a; asm("{ .reg .u64 t; cvta.to.shared.u64 t, %1; cvt.u32.u64 %0, t; }" : "=r"(a) : "l"(p));
    return a;
}

// ---------------- warp-MMA + cp.async helpers (baseline PTX, works at compute_103) ----------------
#define LDSM_X4(r, a) \
    asm volatile("ldmatrix.sync.aligned.m8n8.x4.shared.b16 {%0,%1,%2,%3}, [%4];" \
        : "=r"((r)[0]), "=r"((r)[1]), "=r"((r)[2]), "=r"((r)[3]) : "r"(a))

#define MMA16816(d, a, b0, b1) \
    asm volatile("mma.sync.aligned.m16n8k16.row.col.f32.bf16.bf16.f32 " \
        "{%0,%1,%2,%3},{%4,%5,%6,%7},{%8,%9},{%0,%1,%2,%3};" \
        : "+f"((d)[0]), "+f"((d)[1]), "+f"((d)[2]), "+f"((d)[3]) \
        : "r"((a)[0]), "r"((a)[1]), "r"((a)[2]), "r"((a)[3]), "r"(b0), "r"(b1))

#define CP_ASYNC16(dst, src) \
    asm volatile("cp.async.cg.shared.global [%0], [%1], 16;" :: "r"(dst), "l"(src))
#define CP_COMMIT() asm volatile("cp.async.commit_group;" ::: "memory")
#define CP_WAIT1()  asm volatile("cp.async.wait_group 1;" ::: "memory")
#define CP_WAIT0()  asm volatile("cp.async.wait_group 0;" ::: "memory")

// ---------------- device scratch ----------------
__device__ float g_Wk[Dc*CINc], g_Wv[Dc*CINc], g_Wq[Dc*CINc];
__device__ float g_bk2[Dc], g_bv2[Dc], g_bq2[Dc];
__device__ float g_Wa1f[AHc*Dc];
__device__ float g_ba1f[AHc];
__device__ float g_Wp1f[PHc*3];
__device__ float g_bp1f[PHc];
__device__ __nv_bfloat16 g_Wa1h[AHc*Dc];   // [j][k] row-major
__device__ __nv_bfloat16 g_Wa2h[Dc*AHc];   // [c][j] row-major
__device__ float g_key[Bc*Nc*Dc];   // point-major (b,n,c)
__device__ float g_valv[Bc*Nc*Dc];  // point-major
__device__ float g_qry[Bc*Nc*Dc];   // point-major
__device__ int   g_idx[Bc*Nc*Kc];
__device__ float g_pd[(size_t)Bc*NCH*Nc*16];   // partial knn dists
__device__ int   g_pi[(size_t)Bc*NCH*Nc*16];   // partial knn indices
__device__ __nv_bfloat16 g_Xh[(size_t)Bc*Pc*Dc];  // (b,p,c) bf16: qk_rel+pe
__device__ float g_PE[(size_t)Bc*Pc*Dc];          // (b,p,c) fp32: pe
__device__ __nv_bfloat16 g_H[(size_t)Bc*Pc*AHc];  // (b,p,j) bf16: relu hidden
__device__ float g_agg[Bc*Dc*Nc];                 // (b,c,n)

// ---------------- weight composition ----------------
__global__ void compose_kernel(const float* __restrict__ Wk, const float* __restrict__ bk,
                               const float* __restrict__ Wq, const float* __restrict__ bq,
                               const float* __restrict__ Wv, const float* __restrict__ bv,
                               const float* __restrict__ W_lsq, const float* __restrict__ b_lsq,
                               const float* __restrict__ W_lso, const float* __restrict__ b_lso)
{
    int id = blockIdx.x*256 + threadIdx.x;
    const int total = 3*Dc*CINc;
    if (id < total) {
        int which = id / (Dc*CINc);
        int r = id % (Dc*CINc);
        int o = r / CINc, i = r % CINc;
        const float* A = (which==0) ? Wk : ((which==1) ? Wv : Wq);
        const float* L = (which==2) ? W_lsq : W_lso;
        float s = 0.f;
        #pragma unroll 4
        for (int t = 0; t < Dc; t++) s = fmaf(A[o*Dc+t], L[t*CINc+i], s);
        float* Od = (which==0) ? g_Wk : ((which==1) ? g_Wv : g_Wq);
        Od[o*CINc+i] = s;
    } else if (id < total + 3*Dc) {
        int r = id - total; int which = r / Dc; int o = r % Dc;
        const float* A  = (which==0) ? Wk : ((which==1) ? Wv : Wq);
        const float* bb = (which==0) ? bk : ((which==1) ? bv : bq);
        const float* lb = (which==2) ? b_lsq : b_lso;
        float s = bb[o];
        #pragma unroll 4
        for (int t = 0; t < Dc; t++) s = fmaf(A[o*Dc+t], lb[t], s);
        float* Od = (which==0) ? g_bk2 : ((which==1) ? g_bv2 : g_bq2);
        Od[o] = s;
    }
}

// ---------------- BN folding ----------------
__global__ void fold_kernel(const float* __restrict__ Wa1, const float* __restrict__ ba1,
                            const float* __restrict__ g2,  const float* __restrict__ bt2,
                            const float* __restrict__ m2,  const float* __restrict__ v2,
                            const float* __restrict__ Wp1, const float* __restrict__ bp1,
                            const float* __restrict__ g1,  const float* __restrict__ bt1,
                            const float* __restrict__ m1,  const float* __restrict__ v1)
{
    int id = blockIdx.x*256 + threadIdx.x;
    if (id < AHc*Dc) {
        int j = id / Dc;
        float sc = g2[j] * rsqrtf(v2[j] + EPSc);
        g_Wa1f[id] = sc * Wa1[id];
        return;
    }
    int r = id - AHc*Dc;
    if (r < AHc) {
        float sc = g2[r] * rsqrtf(v2[r] + EPSc);
        g_ba1f[r] = sc*ba1[r] + bt2[r] - m2[r]*sc;
        return;
    }
    r -= AHc;
    if (r < PHc*3) {
        int j = r / 3;
        float sc = g1[j] * rsqrtf(v1[j] + EPSc);
        g_Wp1f[r] = sc * Wp1[r];
        return;
    }
    r -= PHc*3;
    if (r < PHc) {
        float sc = g1[r] * rsqrtf(v1[r] + EPSc);
        g_bp1f[r] = sc*bp1[r] + bt1[r] - m1[r]*sc;
    }
}

// ---------------- bf16 weight conversion (after fold) ----------------
__global__ void tobf16_kernel(const float* __restrict__ Wa2)
{
    int i = blockIdx.x*256 + threadIdx.x;
    if (i < AHc*Dc) {
        g_Wa1h[i] = __float2bfloat16(g_Wa1f[i]);
        g_Wa2h[i] = __float2bfloat16(Wa2[i]);
    }
}

// ---------------- KNN part 1: per-chunk top-16 (512 candidates/chunk, 128-thr blocks) ----------------
__global__ void knn_part_kernel(const float* __restrict__ pos)
{
    __shared__ __align__(16) float4 sc[CH];
    int b = blockIdx.z, ch = blockIdx.y;
    int tid = threadIdx.x;
    int c0 = ch * CH;
    for (int q = tid; q < CH; q += 128) {
        float x = pos[(b*3+0)*Nc + c0 + q];
        float y = pos[(b*3+1)*Nc + c0 + q];
        float z = pos[(b*3+2)*Nc + c0 + q];
        sc[q] = make_float4(x, y, z, fmaf(z, z, fmaf(y, y, x*x)));
    }
    __syncthreads();
    int n = blockIdx.x*128 + tid;
    float qx = pos[(b*3+0)*Nc + n];
    float qy = pos[(b*3+1)*Nc + n];
    float qz = pos[(b*3+2)*Nc + n];
    float qs = fmaf(qz, qz, fmaf(qy, qy, qx*qx));

    float bd[16]; int bi[16];
    #pragma unroll
    for (int t = 0; t < 16; t++) { bd[t] = 3.4e38f; bi[t] = 0; }
    float mx = 3.4e38f; int mp = 0;
    for (int m = 0; m < CH; m++) {
        float4 c = sc[m];
        float dot = fmaf(qz, c.z, fmaf(qy, c.y, qx*c.x));
        float d = (qs + c.w) - 2.0f*dot;
        if (d < mx) {
            bd[mp] = d; bi[mp] = c0 + m;
            mx = bd[0]; mp = 0;
            #pragma unroll
            for (int t = 1; t < 16; t++) if (bd[t] > mx) { mx = bd[t]; mp = t; }
        }
    }
    size_t base = ((size_t)(b*NCH + ch)*Nc + n)*16;
    #pragma unroll
    for (int t = 0; t < 16; t++) { g_pd[base + t] = bd[t]; g_pi[base + t] = bi[t]; }
}

// ---------------- KNN part 2: merge NCHx16 partials (chunk-ascending = index-ascending) ----------------
__global__ void knn_merge_kernel()
{
    int id = blockIdx.x*256 + threadIdx.x;   // 0 .. Bc*Nc-1
    int b = id >> 12, n = id & (Nc-1);
    float bd[16]; int bi[16];
    #pragma unroll
    for (int t = 0; t < 16; t++) { bd[t] = 3.4e38f; bi[t] = 0; }
    float mx = 3.4e38f; int mp = 0;
    for (int ch = 0; ch < NCH; ch++) {
        size_t base = ((size_t)(b*NCH + ch)*Nc + n)*16;
        #pragma unroll
        for (int t = 0; t < 16; t++) {
            float d = g_pd[base + t];
            if (d < mx) {
                bd[mp] = d; bi[mp] = g_pi[base + t];
                mx = bd[0]; mp = 0;
                #pragma unroll
                for (int u = 1; u < 16; u++) if (bd[u] > mx) { mx = bd[u]; mp = u; }
            }
        }
    }
    #pragma unroll
    for (int t = 0; t < 16; t++) g_idx[(b*Nc+n)*16 + t] = bi[t];
}

// ---------------- tiled fp32 GEMM (small pre/post convs) ----------------
template<int O, int I, bool POINT_MAJOR>
__global__ void gemm_kernel(const float* __restrict__ W, const float* __restrict__ bias,
                            const float* __restrict__ In, float* __restrict__ Out)
{
    __shared__ float Wt[64][33];
    __shared__ float Xt[32][64];
    int b  = blockIdx.z;
    int n0 = blockIdx.x*64, o0 = blockIdx.y*64;
    int tid = threadIdx.x, tx = tid & 15, ty = tid >> 4;
    float acc[4][4];
    #pragma unroll
    for (int r = 0; r < 4; r++)
        #pragma unroll
        for (int c = 0; c < 4; c++) acc[r][c] = 0.f;

    for (int k0 = 0; k0 < I; k0 += 32) {
        for (int q = tid; q < 64*32; q += 256) {
            int oo = q >> 5, kk = q & 31;
            Wt[oo][kk] = W[(o0+oo)*I + k0 + kk];
        }
        for (int q = tid; q < 32*64; q += 256) {
            int kk = q >> 6, nn = q & 63;
            Xt[kk][nn] = In[((size_t)b*I + k0 + kk)*Nc + n0 + nn];
        }
        __syncthreads();
        #pragma unroll 8
        for (int kk = 0; kk < 32; kk++) {
            float a[4], bb[4];
            #pragma unroll
            for (int r = 0; r < 4; r++) a[r]  = Wt[ty*4+r][kk];
            #pragma unroll
            for (int c = 0; c < 4; c++) bb[c] = Xt[kk][tx*4+c];
            #pragma unroll
            for (int r = 0; r < 4; r++)
                #pragma unroll
                for (int c = 0; c < 4; c++) acc[r][c] = fmaf(a[r], bb[c], acc[r][c]);
        }
        __syncthreads();
    }
    #pragma unroll
    for (int r = 0; r < 4; r++) {
        float bv = bias[o0 + ty*4 + r];
        #pragma unroll
        for (int c = 0; c < 4; c++) {
            float v = acc[r][c] + bv;
            int oo = o0 + ty*4 + r, nn = n0 + tx*4 + c;
            if (POINT_MAJOR)
                Out[((size_t)b*Nc + nn)*O + oo] = v;
            else
                Out[((size_t)b*O + oo)*Nc + nn] = v;
        }
    }
}

// ---------------- build X (bf16) = q - k_gather + pe, PE (fp32) = pe ----------------
__global__ void build_kernel(const float* __restrict__ pos,
                             const float* __restrict__ Wp2,
                             const float* __restrict__ bp2)
{
    __shared__ float pr[3][64];
    __shared__ __align__(16) float sh[PHc*64];
    __shared__ int sidx[64];
    int b = blockIdx.y;
    int nbase = blockIdx.x*4;
    int pbase = nbase*16;
    int tid = threadIdx.x;

    if (tid < 64) sidx[tid] = g_idx[(b*Nc + nbase)*16 + tid];
    __syncthreads();
    if (tid < 192) {
        int d = tid >> 6, pp = tid & 63;
        int n  = nbase + (pp >> 4);
        int nb = sidx[pp];
        pr[d][pp] = pos[(b*3+d)*Nc + n] - pos[(b*3+d)*Nc + nb];
    }
    __syncthreads();
    for (int q = tid; q < PHc*64; q += 256) {
        int j = q >> 6, pp = q & 63;
        float h = fmaf(g_Wp1f[j*3+2], pr[2][pp],
                  fmaf(g_Wp1f[j*3+1], pr[1][pp],
                  fmaf(g_Wp1f[j*3+0], pr[0][pp], g_bp1f[j])));
        sh[q] = fmaxf(h, 0.f);
    }
    __syncthreads();

    int c = tid;
    float q4[4];
    #pragma unroll
    for (int l = 0; l < 4; l++) q4[l] = g_qry[((size_t)b*Nc + nbase + l)*Dc + c];
    float bc = bp2[c];

    ull A[32];
    #pragma unroll
    for (int g = 0; g < 32; g++) A[g] = pk2(bc, bc);
    const ull* HP = (const ull*)sh;
    #pragma unroll 2
    for (int j = 0; j < PHc; j++) {
        float w = Wp2[c*PHc + j];
        ull wb = pk2(w, w);
        const ull* hp = HP + j*32;
        #pragma unroll
        for (int g = 0; g < 32; g++) A[g] = fma2(wb, hp[g], A[g]);
    }
    #pragma unroll
    for (int g = 0; g < 32; g++) {
        float p0, p1; upk2(A[g], p0, p1);
        int pp0 = g*2;
        #pragma unroll
        for (int u = 0; u < 2; u++) {
            int pp = pp0 + u;
            float pe = (u == 0) ? p0 : p1;
            int nb = sidx[pp];
            int nl = pp >> 4;
            size_t kb = ((size_t)b*Nc + nb)*Dc + c;
            size_t ob = ((size_t)b*Pc + pbase + pp)*Dc + c;
            g_Xh[ob] = __float2bfloat16(q4[nl] - g_key[kb] + pe);
            g_PE[ob] = pe;
        }
    }
}

// ---------------- warp-MMA core with cp.async double buffering ----------------
// acc[p 128 x n 256] += A[128 x K] · B[256 x K]^T
// Block: 512 threads = 16 warps (8 row-warps x 2 col-warps).
// smem: A buffers [2][128*SMPITCH], B buffers [2][256*SMPITCH] = 110592 B.
#define SMPITCH 144
#define SMEM_MMA (2*128*SMPITCH + 2*256*SMPITCH)   /* 110592 B */

template<int KTOT>
__device__ __forceinline__ void mma_core(char* sm,
                                         const __nv_bfloat16* __restrict__ gA,
                                         const __nv_bfloat16* __restrict__ gB,
                                         float (&acc)[16][4])
{
    uint32_t sA = smem_u32(sm);
    uint32_t sB = sA + 2*128*SMPITCH;
    int tid = threadIdx.x;
    int lane = tid & 31, wid = tid >> 5;
    int wr = wid >> 1, wc = wid & 1;

    uint32_t aOff = (uint32_t)(wr*16 + (lane & 15))*SMPITCH + (uint32_t)((lane >> 4) << 4);
    uint32_t bOff = (uint32_t)(wc*128 + (lane & 15))*SMPITCH + (uint32_t)((lane >> 4) << 4);

    const int NS = KTOT/64;
    int arow = tid >> 3, ac8 = (tid & 7) << 3;
    #define MMA_ISSUE(s, buf) do { \
        uint32_t dA = sA + (buf)*(128*SMPITCH); \
        uint32_t dB = sB + (buf)*(256*SMPITCH); \
        _Pragma("unroll") \
        for (int it = 0; it < 2; it++) { \
            int row = arow + it*64; \
            CP_ASYNC16(dA + row*SMPITCH + ac8*2, gA + (size_t)row*KTOT + (s)*64 + ac8); \
        } \
        _Pragma("unroll") \
        for (int it = 0; it < 4; it++) { \
            int row = arow + it*64; \
            CP_ASYNC16(dB + row*SMPITCH + ac8*2, gB + (size_t)row*KTOT + (s)*64 + ac8); \
        } \
        CP_COMMIT(); \
    } while(0)

    MMA_ISSUE(0, 0);
    for (int i = 0; i < NS; i++) {
        if (i + 1 < NS) { MMA_ISSUE(i+1, (i+1)&1); CP_WAIT1(); }
        else            { CP_WAIT0(); }
        __syncthreads();
        uint32_t aAddr = sA + (i&1)*(128*SMPITCH) + aOff;
        uint32_t bAddr = sB + (i&1)*(256*SMPITCH) + bOff;
        #pragma unroll
        for (int ks = 0; ks < 4; ks++) {
            uint32_t a[4];
            LDSM_X4(a, aAddr + ks*32);
            #pragma unroll
            for (int tp = 0; tp < 8; tp++) {
                uint32_t q[4];
                LDSM_X4(q, bAddr + tp*16*SMPITCH + ks*32);
                MMA16816(acc[2*tp],   a, q[0], q[2]);
                MMA16816(acc[2*tp+1], a, q[1], q[3]);
            }
        }
        __syncthreads();
    }
    #undef MMA_ISSUE
}

// ---------------- mlp1: H = relu(X · Wa1^T + b1) -> bf16 ----------------
__global__ void __launch_bounds__(512, 1) mlp1_kernel()
{
    extern __shared__ __align__(16) char sm1[];
    int b = blockIdx.z;
    int ptile = blockIdx.x*128;
    int j0 = blockIdx.y*256;
    const __nv_bfloat16* gA = g_Xh + ((size_t)b*Pc + ptile)*Dc;
    const __nv_bfloat16* gB = g_Wa1h + (size_t)j0*Dc;

    float acc[16][4];
    #pragma unroll
    for (int t = 0; t < 16; t++)
        #pragma unroll
        for (int q = 0; q < 4; q++) acc[t][q] = 0.f;

    mma_core<Dc>(sm1, gA, gB, acc);

    int tid = threadIdx.x, lane = tid & 31, wid = tid >> 5;
    int wr = wid >> 1, wc = wid & 1;
    int prow = ptile + wr*16 + (lane >> 2);
    __nv_bfloat16* H0 = g_H + ((size_t)b*Pc + prow)*AHc + j0;
    __nv_bfloat16* H1 = H0 + (size_t)8*AHc;
    #pragma unroll
    for (int t = 0; t < 16; t++) {
        int c = wc*128 + t*8 + ((lane & 3) << 1);
        float b0 = g_ba1f[j0 + c], b1 = g_ba1f[j0 + c + 1];
        float r00 = fmaxf(acc[t][0] + b0, 0.f);
        float r01 = fmaxf(acc[t][1] + b1, 0.f);
        float r10 = fmaxf(acc[t][2] + b0, 0.f);
        float r11 = fmaxf(acc[t][3] + b1, 0.f);
        uint32_t u0, u1;
        asm("cvt.rn.bf16x2.f32 %0, %1, %2;" : "=r"(u0) : "f"(r01), "f"(r00));
        asm("cvt.rn.bf16x2.f32 %0, %1, %2;" : "=r"(u1) : "f"(r11), "f"(r10));
        *(uint32_t*)(H0 + c) = u0;
        *(uint32_t*)(H1 + c) = u1;
    }
}

// ---------------- mlp2: logits = H · Wa2^T, fused softmax(K=16) + aggregate ----------------
__global__ void __launch_bounds__(512, 1) mlp2_kernel()
{
    extern __shared__ __align__(16) char sm2[];
    int b = blockIdx.z;
    int ptile = blockIdx.x*128;
    const __nv_bfloat16* gA = g_H + ((size_t)b*Pc + ptile)*AHc;
    const __nv_bfloat16* gB = g_Wa2h;

    float acc[16][4];
    #pragma unroll
    for (int t = 0; t < 16; t++)
        #pragma unroll
        for (int q = 0; q < 4; q++) acc[t][q] = 0.f;

    mma_core<AHc>(sm2, gA, gB, acc);

    int tid = threadIdx.x, lane = tid & 31, wid = tid >> 5;
    int wr = wid >> 1, wc = wid & 1;
    int n = (ptile >> 4) + wr;
    const float* peRow = g_PE + ((size_t)b*Pc + ptile + wr*16 + (lane >> 2))*Dc;
    const float* valRow = g_valv + ((size_t)b*Nc + n)*Dc;
    float* aggCol = g_agg + (size_t)b*Dc*Nc + n;

    #pragma unroll
    for (int t = 0; t < 16; t++) {
        int c = wc*128 + t*8 + ((lane & 3) << 1);
        float m0 = fmaxf(acc[t][0], acc[t][2]);
        float m1 = fmaxf(acc[t][1], acc[t][3]);
        #pragma unroll
        for (int d = 4; d <= 16; d <<= 1) {
            m0 = fmaxf(m0, __shfl_xor_sync(0xffffffffu, m0, d));
            m1 = fmaxf(m1, __shfl_xor_sync(0xffffffffu, m1, d));
        }
        float e0 = __expf(acc[t][0] - m0), e2 = __expf(acc[t][2] - m0);
        float e1 = __expf(acc[t][1] - m1), e3 = __expf(acc[t][3] - m1);
        float s0 = e0 + e2, s1 = e1 + e3;
        #pragma unroll
        for (int d = 4; d <= 16; d <<= 1) {
            s0 += __shfl_xor_sync(0xffffffffu, s0, d);
            s1 += __shfl_xor_sync(0xffffffffu, s1, d);
        }
        float2 p0 = *(const float2*)(peRow + c);
        float2 p1 = *(const float2*)(peRow + 8*Dc + c);
        float a0 = e0*p0.x + e2*p1.x;
        float a1 = e1*p0.y + e3*p1.y;
        #pragma unroll
        for (int d = 4; d <= 16; d <<= 1) {
            a0 += __shfl_xor_sync(0xffffffffu, a0, d);
            a1 += __shfl_xor_sync(0xffffffffu, a1, d);
        }
        if (lane < 4) {
            aggCol[(size_t)c*Nc]       = a0/s0 + valRow[c];
            aggCol[(size_t)(c+1)*Nc]   = a1/s1 + valRow[c+1];
        }
    }
}

// ---------------- launch ----------------
extern "C" void kernel_launch(void* const* d_in, const int* in_sizes, int n_in,
                              void* d_out, int out_size)
{
    const float* obj   = (const float*)d_in[0];
    const float* pos   = (const float*)d_in[1];
    const float* qp    = (const float*)d_in[2];
    const float* W_lsq = (const float*)d_in[3];  const float* b_lsq = (const float*)d_in[4];
    const float* W_lso = (const float*)d_in[5];  const float* b_lso = (const float*)d_in[6];
    const float* Wk    = (const float*)d_in[7];  const float* bk    = (const float*)d_in[8];
    const float* Wq    = (const float*)d_in[9];  const float* bq    = (const float*)d_in[10];
    const float* Wv    = (const float*)d_in[11]; const float* bv    = (const float*)d_in[12];
    const float* Wp1   = (const float*)d_in[13]; const float* bp1   = (const float*)d_in[14];
    const float* g1    = (const float*)d_in[15]; const float* bt1   = (const float*)d_in[16];
    const float* m1    = (const float*)d_in[17]; const float* v1    = (const float*)d_in[18];
    const float* Wp2   = (const float*)d_in[19]; const float* bp2   = (const float*)d_in[20];
    const float* Wa1   = (const float*)d_in[21]; const float* ba1   = (const float*)d_in[22];
    const float* g2    = (const float*)d_in[23]; const float* bt2   = (const float*)d_in[24];
    const float* m2    = (const float*)d_in[25]; const float* v2    = (const float*)d_in[26];
    const float* Wa2   = (const float*)d_in[27]; /* ba2 (d_in[28]) cancels in softmax */
    const float* We    = (const float*)d_in[29]; const float* bfin  = (const float*)d_in[30];
    float* out = (float*)d_out;

    cudaFuncSetAttribute(mlp1_kernel, cudaFuncAttributeMaxDynamicSharedMemorySize, SMEM_MMA);
    cudaFuncSetAttribute(mlp2_kernel, cudaFuncAttributeMaxDynamicSharedMemorySize, SMEM_MMA);

    void *pWk, *pWv, *pWq, *pbk, *pbv, *pbq, *pkey, *pval, *pqry, *pagg;
    cudaGetSymbolAddress(&pWk, g_Wk);   cudaGetSymbolAddress(&pWv, g_Wv);
    cudaGetSymbolAddress(&pWq, g_Wq);   cudaGetSymbolAddress(&pbk, g_bk2);
    cudaGetSymbolAddress(&pbv, g_bv2);  cudaGetSymbolAddress(&pbq, g_bq2);
    cudaGetSymbolAddress(&pkey, g_key); cudaGetSymbolAddress(&pval, g_valv);
    cudaGetSymbolAddress(&pqry, g_qry); cudaGetSymbolAddress(&pagg, g_agg);

    compose_kernel<<<387, 256>>>(Wk, bk, Wq, bq, Wv, bv, W_lsq, b_lsq, W_lso, b_lso);
    fold_kernel<<<1029, 256>>>(Wa1, ba1, g2, bt2, m2, v2, Wp1, bp1, g1, bt1, m1, v1);
    tobf16_kernel<<<1024, 256>>>(Wa2);

    knn_part_kernel<<<dim3(Nc/128, NCH, Bc), 128>>>(pos);
    knn_merge_kernel<<<Bc*Nc/256, 256>>>();

    gemm_kernel<Dc, CINc, true><<<dim3(Nc/64, Dc/64, Bc), 256>>>((const float*)pWk, (const float*)pbk, obj, (float*)pkey);
    gemm_kernel<Dc, CINc, true><<<dim3(Nc/64, Dc/64, Bc), 256>>>((const float*)pWv, (const float*)pbv, obj, (float*)pval);
    gemm_kernel<Dc, CINc, true><<<dim3(Nc/64, Dc/64, Bc), 256>>>((const float*)pWq, (const float*)pbq, qp,  (float*)pqry);

    build_kernel<<<dim3(Nc/4, Bc), 256>>>(pos, Wp2, bp2);

    mlp1_kernel<<<dim3(Pc/128, AHc/256, Bc), 512, SMEM_MMA>>>();
    mlp2_kernel<<<dim3(Pc/128, 1, Bc), 512, SMEM_MMA>>>();

    gemm_kernel<CINc, Dc, false><<<dim3(Nc/64, CINc/64, Bc), 256>>>(We, bfin, (const float*)pagg, out);
}